// round 6
// baseline (speedup 1.0000x reference)
#include <cuda_runtime.h>
#include <cuda_bf16.h>
#include <cstdint>

// ---------------- problem constants ----------------
#define BATCH 8
#define CCH   64
#define HH    64
#define WW    64
#define NPOS  4096
#define LSEQ  77
#define DTXT  512
#define NBLK  16
#define NHEAD 8
#define HDIM  8

// ---------------- device scratch ----------------
__device__ float g_tf  [BATCH*LSEQ*CCH];
__device__ float g_kn  [NBLK*BATCH*LSEQ*CCH];
__device__ float g_v   [NBLK*BATCH*LSEQ*CCH];
__device__ float g_feat[BATCH*CCH*HH*WW];
__device__ float g_u1  [BATCH*CCH*128*128];
__device__ float g_u2  [(size_t)BATCH*CCH*256*256];
__device__ float g_wupT[2*9*64*256];          // [lvl][tap][ic][oc4], tf32-rounded

__device__ __forceinline__ float to_tf32(float x) {
    float r; asm("cvt.rna.tf32.f32 %0, %1;" : "=f"(r) : "f"(x)); return r;
}
__device__ __forceinline__ void mma_tf32(float* d, const uint32_t* a, const uint32_t* b) {
    asm volatile(
        "mma.sync.aligned.m16n8k8.row.col.f32.tf32.tf32.f32 "
        "{%0,%1,%2,%3}, {%4,%5,%6,%7}, {%8,%9}, {%0,%1,%2,%3};"
        : "+f"(d[0]), "+f"(d[1]), "+f"(d[2]), "+f"(d[3])
        : "r"(a[0]), "r"(a[1]), "r"(a[2]), "r"(a[3]), "r"(b[0]), "r"(b[1]));
}
// permuted channel index: ic = ks*8 + tig + 4h  ->  pic = ks*8 + tig*2 + h
__device__ __forceinline__ int picf(int ic) {
    int r = ic & 7;
    return (ic & ~7) + ((r & 3) * 2) + (r >> 2);
}

// ---------------- text projection (+ fused tf32 up-weight transpose) ----------------
__global__ void k_textproj(const float* __restrict__ th,
                           const float* __restrict__ pw,
                           const float* __restrict__ pb,
                           const float* __restrict__ upw) {
    __shared__ float s[DTXT];
    int bl = blockIdx.x;
    const float* row = th + (size_t)bl * DTXT;
    for (int i = threadIdx.x; i < DTXT; i += 64) s[i] = row[i];
    __syncthreads();
    int c = threadIdx.x;
    const float* w = pw + (size_t)c * DTXT;
    float acc = pb[c];
#pragma unroll 8
    for (int d = 0; d < DTXT; ++d) acc += s[d] * w[d];
    g_tf[bl * CCH + c] = acc;
    // transpose up weights [lvl,oc4,ic,k] -> [lvl,k,ic,oc4], rounded to tf32
    for (int idx = blockIdx.x * 64 + threadIdx.x; idx < 2 * 256 * 64 * 9;
         idx += gridDim.x * 64) {
        int k = idx % 9;
        int t = idx / 9;
        int ic = t % 64; t /= 64;
        int oc4 = t % 256;
        int lvl = t / 256;
        g_wupT[(((lvl * 9 + k) * 64 + ic) * 256) + oc4] = to_tf32(upw[idx]);
    }
}

// ---------------- input conv 3->64, 3x3 ----------------
__global__ void k_convin(const float* __restrict__ x,
                         const float* __restrict__ w,
                         const float* __restrict__ bias) {
    __shared__ float sw[64 * 27];
    __shared__ float sb[64];
    __shared__ float sin_[3][3][66];
    int bid = blockIdx.x; int b = bid >> 6; int y = bid & 63;
    int tid = threadIdx.x;
    for (int i = tid; i < 64 * 27; i += 64) sw[i] = w[i];
    sb[tid] = bias[tid];
    for (int ic = 0; ic < 3; ic++)
        for (int r = 0; r < 3; r++) {
            int yy = y + r - 1;
            float v = 0.f;
            if (yy >= 0 && yy < HH) v = x[(((size_t)b * 3 + ic) * HH + yy) * WW + tid];
            sin_[ic][r][tid + 1] = v;
            if (tid == 0) { sin_[ic][r][0] = 0.f; sin_[ic][r][65] = 0.f; }
        }
    __syncthreads();
    int xx = tid;
    for (int oc = 0; oc < 64; oc++) {
        float acc = sb[oc];
#pragma unroll
        for (int ic = 0; ic < 3; ic++)
#pragma unroll
            for (int r = 0; r < 3; r++)
#pragma unroll
                for (int kx = 0; kx < 3; kx++)
                    acc += sin_[ic][r][xx + kx] * sw[(oc * 3 + ic) * 9 + r * 3 + kx];
        g_feat[(((size_t)b * CCH + oc) * HH + y) * WW + xx] = acc;
    }
}

// ---------------- K/V projection + LN(K), all blocks, L-split ----------------
__global__ void __launch_bounds__(256) k_kvall(
        const float* __restrict__ kw, const float* __restrict__ kb,
        const float* __restrict__ vw, const float* __restrict__ vb,
        const float* __restrict__ l2w, const float* __restrict__ l2b) {
    __shared__ float tfs[LSEQ * 64];
    __shared__ float kws[64 * 68];
    __shared__ float vws[64 * 68];
    __shared__ float ksm[4 * 64];
    int blk = blockIdx.x, b = blockIdx.y, z = blockIdx.z;
    int tid = threadIdx.x;
    for (int i = tid; i < LSEQ * 64; i += 256) tfs[i] = g_tf[b * LSEQ * 64 + i];
    for (int idx = tid; idx < 4096; idx += 256) {
        int o = idx >> 6, c = idx & 63;
        kws[c * 68 + o] = kw[blk * 4096 + idx];
        vws[c * 68 + o] = vw[blk * 4096 + idx];
    }
    __syncthreads();
    int o = tid & 63, rr = tid >> 6;
    float kbv = kb[blk * 64 + o], vbv = vb[blk * 64 + o];
    float lwv = l2w[blk * 64 + o], lbv = l2b[blk * 64 + o];
    size_t base = ((size_t)(blk * BATCH + b)) * LSEQ * 64;
    int rbeg = z * 40, rend = rbeg + 40;
    for (int r0 = rbeg; r0 < rend; r0 += 4) {
        int r = r0 + rr;
        bool act = r < LSEQ;
        float ka = kbv, va = vbv;
        if (act) {
#pragma unroll 8
            for (int c = 0; c < 64; c++) {
                float t = tfs[r * 64 + c];
                ka += t * kws[c * 68 + o];
                va += t * vws[c * 68 + o];
            }
            ksm[rr * 64 + o] = ka;
        }
        __syncthreads();
        if (act) {
            float m = 0.f;
#pragma unroll 8
            for (int i = 0; i < 64; i++) m += ksm[rr * 64 + i];
            m *= (1.f / 64.f);
            float vv = 0.f;
#pragma unroll 8
            for (int i = 0; i < 64; i++) { float d = ksm[rr * 64 + i] - m; vv += d * d; }
            vv *= (1.f / 64.f);
            float rs = rsqrtf(vv + 1e-5f);
            g_kn[base + r * 64 + o] = (ka - m) * rs * lwv + lbv;
            g_v [base + r * 64 + o] = va;
        }
        __syncthreads();
    }
}

// ---------------- FUSED attention stack (16 blocks, one launch) ----------------
__global__ void __launch_bounds__(256, 3) k_attn_stack(
        const float* __restrict__ qw, const float* __restrict__ qb,
        const float* __restrict__ ow, const float* __restrict__ ob,
        const float* __restrict__ l1w, const float* __restrict__ l1b) {
    __shared__ __align__(16) float rA[LSEQ * 64];   // Wq | K
    __shared__ __align__(16) float rB[LSEQ * 64];   // V | Wo
    __shared__ __align__(16) float sF[64 * 64];
    __shared__ __align__(16) float sQ[64 * 68];

    int b = blockIdx.x >> 6, y = blockIdx.x & 63;
    int tid = threadIdx.x;

    for (int idx = tid; idx < 4096; idx += 256)
        sF[idx] = g_feat[(((size_t)b * 64 + (idx >> 6)) * 64 + y) * 64 + (idx & 63)];

    float pey = (float)y * (0.05f / 63.f);
    const float scale = 0.35355339059327373f;

#pragma unroll 1
    for (int blk = 0; blk < NBLK; blk++) {
        size_t kvbase = ((size_t)(blk * BATCH + b)) * LSEQ * 64;
        __syncthreads();
        for (int idx = tid; idx < 4096; idx += 256) {
            int o = idx >> 6, i = idx & 63;
            rA[i * 68 + o] = qw[blk * 4096 + idx];
        }
        for (int i = tid; i < LSEQ * 64; i += 256) rB[i] = g_v[kvbase + i];
        __syncthreads();

        // ---- phase B: q-proj + pe + LN ----
        {
            int og = tid & 15, xg = tid >> 4;
            int o0 = og * 4, x0 = xg * 4;
            float4 bq = *(const float4*)&qb[blk * 64 + o0];
            float acc[4][4];
#pragma unroll
            for (int xi = 0; xi < 4; xi++) {
                acc[xi][0] = bq.x; acc[xi][1] = bq.y; acc[xi][2] = bq.z; acc[xi][3] = bq.w;
            }
#pragma unroll 8
            for (int i = 0; i < 64; i++) {
                float4 fx = *(const float4*)&sF[i * 64 + x0];
                float4 wv = *(const float4*)&rA[i * 68 + o0];
                acc[0][0] += fx.x * wv.x; acc[0][1] += fx.x * wv.y; acc[0][2] += fx.x * wv.z; acc[0][3] += fx.x * wv.w;
                acc[1][0] += fx.y * wv.x; acc[1][1] += fx.y * wv.y; acc[1][2] += fx.y * wv.z; acc[1][3] += fx.y * wv.w;
                acc[2][0] += fx.z * wv.x; acc[2][1] += fx.z * wv.y; acc[2][2] += fx.z * wv.z; acc[2][3] += fx.z * wv.w;
                acc[3][0] += fx.w * wv.x; acc[3][1] += fx.w * wv.y; acc[3][2] += fx.w * wv.z; acc[3][3] += fx.w * wv.w;
            }
            float4 lw = *(const float4*)&l1w[blk * 64 + o0];
            float4 lb = *(const float4*)&l1b[blk * 64 + o0];
#pragma unroll
            for (int xi = 0; xi < 4; xi++) {
                float pex = (float)(x0 + xi) * (0.05f / 63.f);
#pragma unroll
                for (int oj = 0; oj < 4; oj++)
                    acc[xi][oj] += ((o0 + oj) < 32) ? pex : pey;
                float s = acc[xi][0] + acc[xi][1] + acc[xi][2] + acc[xi][3];
#pragma unroll
                for (int off = 1; off < 16; off <<= 1) s += __shfl_xor_sync(0xffffffffu, s, off);
                float mean = s * (1.f / 64.f);
                float d0 = acc[xi][0] - mean, d1 = acc[xi][1] - mean,
                      d2 = acc[xi][2] - mean, d3 = acc[xi][3] - mean;
                float sq = d0 * d0 + d1 * d1 + d2 * d2 + d3 * d3;
#pragma unroll
                for (int off = 1; off < 16; off <<= 1) sq += __shfl_xor_sync(0xffffffffu, sq, off);
                float rs = rsqrtf(sq * (1.f / 64.f) + 1e-5f);
                float4 outv;
                outv.x = d0 * rs * lw.x + lb.x;
                outv.y = d1 * rs * lw.y + lb.y;
                outv.z = d2 * rs * lw.z + lb.z;
                outv.w = d3 * rs * lw.w + lb.w;
                *(float4*)&sQ[(x0 + xi) * 68 + o0] = outv;
            }
        }
        __syncthreads();
        for (int i = tid; i < LSEQ * 64; i += 256) rA[i] = g_kn[kvbase + i];
        __syncthreads();

        // ---- phase C: attention (tree-reduced logits, unrolled) ----
        {
            int hp = tid & 3, pl = tid >> 2;
            int co = hp * 16;
            const float4* qp = (const float4*)&sQ[pl * 68 + co];
            float4 qa0 = qp[0], qa1 = qp[1], qb0 = qp[2], qb1 = qp[3];
            __syncthreads();
            float denA = 0.f, denB = 0.f;
            float4 a0 = make_float4(0, 0, 0, 0), a1 = a0, b0 = a0, b1 = a0;
#pragma unroll 2
            for (int l = 0; l < LSEQ; l++) {
                const float4* kp = (const float4*)&rA[l * 64 + co];
                float4 k0 = kp[0], k1 = kp[1], k2 = kp[2], k3 = kp[3];
                float tA0 = qa0.x * k0.x + qa0.y * k0.y;
                float tA1 = qa0.z * k0.z + qa0.w * k0.w;
                float tA2 = qa1.x * k1.x + qa1.y * k1.y;
                float tA3 = qa1.z * k1.z + qa1.w * k1.w;
                float tB0 = qb0.x * k2.x + qb0.y * k2.y;
                float tB1 = qb0.z * k2.z + qb0.w * k2.w;
                float tB2 = qb1.x * k3.x + qb1.y * k3.y;
                float tB3 = qb1.z * k3.z + qb1.w * k3.w;
                float lgA = (tA0 + tA1) + (tA2 + tA3);
                float lgB = (tB0 + tB1) + (tB2 + tB3);
                float eA = __expf(lgA * scale);
                float eB = __expf(lgB * scale);
                denA += eA; denB += eB;
                const float4* vp = (const float4*)&rB[l * 64 + co];
                float4 v0 = vp[0], v1 = vp[1], v2 = vp[2], v3 = vp[3];
                a0.x += eA * v0.x; a0.y += eA * v0.y; a0.z += eA * v0.z; a0.w += eA * v0.w;
                a1.x += eA * v1.x; a1.y += eA * v1.y; a1.z += eA * v1.z; a1.w += eA * v1.w;
                b0.x += eB * v2.x; b0.y += eB * v2.y; b0.z += eB * v2.z; b0.w += eB * v2.w;
                b1.x += eB * v3.x; b1.y += eB * v3.y; b1.z += eB * v3.z; b1.w += eB * v3.w;
            }
            float iA = 1.f / denA, iB = 1.f / denB;
            sQ[(co + 0) * 68 + pl] = a0.x * iA;  sQ[(co + 1) * 68 + pl] = a0.y * iA;
            sQ[(co + 2) * 68 + pl] = a0.z * iA;  sQ[(co + 3) * 68 + pl] = a0.w * iA;
            sQ[(co + 4) * 68 + pl] = a1.x * iA;  sQ[(co + 5) * 68 + pl] = a1.y * iA;
            sQ[(co + 6) * 68 + pl] = a1.z * iA;  sQ[(co + 7) * 68 + pl] = a1.w * iA;
            sQ[(co + 8) * 68 + pl] = b0.x * iB;  sQ[(co + 9) * 68 + pl] = b0.y * iB;
            sQ[(co + 10) * 68 + pl] = b0.z * iB; sQ[(co + 11) * 68 + pl] = b0.w * iB;
            sQ[(co + 12) * 68 + pl] = b1.x * iB; sQ[(co + 13) * 68 + pl] = b1.y * iB;
            sQ[(co + 14) * 68 + pl] = b1.z * iB; sQ[(co + 15) * 68 + pl] = b1.w * iB;
        }
        __syncthreads();
        for (int idx = tid; idx < 4096; idx += 256) {
            int o = idx >> 6, i = idx & 63;
            rB[i * 68 + o] = ow[blk * 4096 + idx];
        }
        __syncthreads();

        // ---- phase E: out-proj + residual ----
        {
            int xg = tid & 15, og = tid >> 4;
            int x0 = xg * 4, o0 = og * 4;
            float acc[4][4];
#pragma unroll
            for (int oj = 0; oj < 4; oj++)
#pragma unroll
                for (int xi = 0; xi < 4; xi++) acc[oj][xi] = 0.f;
#pragma unroll 8
            for (int i = 0; i < 64; i++) {
                float4 fx = *(const float4*)&sQ[i * 68 + x0];
                float4 wv = *(const float4*)&rB[i * 68 + o0];
                acc[0][0] += wv.x * fx.x; acc[0][1] += wv.x * fx.y; acc[0][2] += wv.x * fx.z; acc[0][3] += wv.x * fx.w;
                acc[1][0] += wv.y * fx.x; acc[1][1] += wv.y * fx.y; acc[1][2] += wv.y * fx.z; acc[1][3] += wv.y * fx.w;
                acc[2][0] += wv.z * fx.x; acc[2][1] += wv.z * fx.y; acc[2][2] += wv.z * fx.z; acc[2][3] += wv.z * fx.w;
                acc[3][0] += wv.w * fx.x; acc[3][1] += wv.w * fx.y; acc[3][2] += wv.w * fx.z; acc[3][3] += wv.w * fx.w;
            }
            float4 bo = *(const float4*)&ob[blk * 64 + o0];
            float bov[4] = { bo.x, bo.y, bo.z, bo.w };
            __syncthreads();
#pragma unroll
            for (int oj = 0; oj < 4; oj++) {
                float* fp = &sF[(o0 + oj) * 64 + x0];
                float4 f = *(float4*)fp;
                f.x += acc[oj][0] + bov[oj];
                f.y += acc[oj][1] + bov[oj];
                f.z += acc[oj][2] + bov[oj];
                f.w += acc[oj][3] + bov[oj];
                *(float4*)fp = f;
            }
        }
    }
    __syncthreads();
    for (int idx = tid; idx < 4096; idx += 256)
        g_feat[(((size_t)b * 64 + (idx >> 6)) * 64 + y) * 64 + (idx & 63)] = sF[idx];
}

// ---------------- TF32 tensor-core up-conv + pixel-shuffle + relu ----------------
// lds.64 fragment loads via permuted channel layout pic().
__global__ void __launch_bounds__(256, 3) k_upconv_tc(int lvl, int IH, int IW,
                                                      const float* __restrict__ up_b) {
    const float* in   = lvl ? g_u1 : g_feat;
    float*       outp = lvl ? g_u2 : g_u1;
    __shared__ float sA[180 * 66];   // [spatial r*18+c][pic(ic)], stride 66
    __shared__ float sBT[64 * 66];   // [oc][pic(ic)], stride 66
    int x0 = blockIdx.x * 16, y0 = blockIdx.y * 8;
    int bz = blockIdx.z; int b = bz >> 2, ocg = bz & 3;
    int tid = threadIdx.x;
    int w = tid >> 5, lane = tid & 31;
    int g = lane >> 2, tig = lane & 3;
    int wm = w & 3, wn = w >> 2;

    // stage input tile with halo (tf32-rounded, permuted channels)
    for (int idx = tid; idx < 180 * 64; idx += 256) {
        int ic = idx / 180; int sp = idx % 180;
        int r = sp / 18, c = sp % 18;
        int gy = y0 - 1 + r, gx = x0 - 1 + c;
        float v = 0.f;
        if (gy >= 0 && gy < IH && gx >= 0 && gx < IW)
            v = in[(((size_t)b * 64 + ic) * IH + gy) * IW + gx];
        sA[sp * 66 + picf(ic)] = to_tf32(v);
    }

    float d[2][4][4];
#pragma unroll
    for (int nt = 0; nt < 4; nt++) {
        int oc = ocg * 64 + wn * 32 + nt * 8 + tig * 2;
        float b0v = up_b[lvl * 256 + oc];
        float b1v = up_b[lvl * 256 + oc + 1];
#pragma unroll
        for (int mt = 0; mt < 2; mt++) {
            d[mt][nt][0] = b0v; d[mt][nt][1] = b1v;
            d[mt][nt][2] = b0v; d[mt][nt][3] = b1v;
        }
    }

#pragma unroll 1
    for (int t = 0; t < 9; t++) {
        int ky = t / 3, kx = t % 3;
        __syncthreads();
        for (int idx = tid; idx < 4096; idx += 256) {
            int ic = idx >> 6, oc = idx & 63;
            sBT[oc * 66 + picf(ic)] =
                g_wupT[(((lvl * 9 + t) * 64 + ic) * 256) + ocg * 64 + oc];
        }
        __syncthreads();
        int sp_base[2][2];
#pragma unroll
        for (int mt = 0; mt < 2; mt++) {
            int m_lo = wm * 32 + mt * 16 + g;
            int m_hi = m_lo + 8;
            sp_base[mt][0] = ((m_lo >> 4) + ky) * 18 + (m_lo & 15) + kx;
            sp_base[mt][1] = ((m_hi >> 4) + ky) * 18 + (m_hi & 15) + kx;
        }
#pragma unroll
        for (int ks = 0; ks < 8; ks++) {
            int po = ks * 8 + tig * 2;
            uint32_t A[2][4];
#pragma unroll
            for (int mt = 0; mt < 2; mt++) {
                float2 lo = *(const float2*)&sA[sp_base[mt][0] * 66 + po];
                float2 hi = *(const float2*)&sA[sp_base[mt][1] * 66 + po];
                A[mt][0] = __float_as_uint(lo.x);
                A[mt][1] = __float_as_uint(hi.x);
                A[mt][2] = __float_as_uint(lo.y);
                A[mt][3] = __float_as_uint(hi.y);
            }
            uint32_t Bf[4][2];
#pragma unroll
            for (int nt = 0; nt < 4; nt++) {
                int nc = wn * 32 + nt * 8 + g;
                float2 bv = *(const float2*)&sBT[nc * 66 + po];
                Bf[nt][0] = __float_as_uint(bv.x);
                Bf[nt][1] = __float_as_uint(bv.y);
            }
#pragma unroll
            for (int mt = 0; mt < 2; mt++)
#pragma unroll
                for (int nt = 0; nt < 4; nt++)
                    mma_tf32(d[mt][nt], A[mt], Bf[nt]);
        }
    }

    int OW = IW * 2;
#pragma unroll
    for (int mt = 0; mt < 2; mt++) {
#pragma unroll
        for (int half = 0; half < 2; half++) {
            int m = wm * 32 + mt * 16 + g + half * 8;
            int gy = y0 + (m >> 4), gx = x0 + (m & 15);
#pragma unroll
            for (int nt = 0; nt < 4; nt++) {
                int oc4a = ocg * 64 + wn * 32 + nt * 8 + tig * 2;
                float v0 = d[mt][nt][half * 2 + 0];
                float v1 = d[mt][nt][half * 2 + 1];
                int ca = oc4a >> 2, r1a = (oc4a >> 1) & 1, r2a = oc4a & 1;
                int oc4b = oc4a + 1;
                int cb = oc4b >> 2, r1b = (oc4b >> 1) & 1, r2b = oc4b & 1;
                outp[(((size_t)b * 64 + ca) * (size_t)(IH * 2) + (size_t)(2 * gy + r1a)) * (size_t)OW
                     + 2 * gx + r2a] = fmaxf(v0, 0.f);
                outp[(((size_t)b * 64 + cb) * (size_t)(IH * 2) + (size_t)(2 * gy + r1b)) * (size_t)OW
                     + 2 * gx + r2b] = fmaxf(v1, 0.f);
            }
        }
    }
}

// ---------------- final conv 64->3 at 256x256 ----------------
__global__ void __launch_bounds__(256) k_cl(const float* __restrict__ w,
                                            const float* __restrict__ bias,
                                            float* __restrict__ out) {
    __shared__ float sw[3 * 64 * 9];
    __shared__ float sin_[4][10][132];
    int xbase = blockIdx.x * 128;
    int y0 = blockIdx.y * 8;
    int b = blockIdx.z;
    int tid = threadIdx.x;
    int xg = tid & 31; int yr = tid >> 5;
    int x0 = xg * 4;
    for (int i = tid; i < 1728; i += 256) sw[i] = w[i];
    float acc[3][4];
#pragma unroll
    for (int oc = 0; oc < 3; oc++) {
        float bb = bias[oc];
#pragma unroll
        for (int xi = 0; xi < 4; xi++) acc[oc][xi] = bb;
    }
    for (int ic0 = 0; ic0 < 64; ic0 += 4) {
        __syncthreads();
        for (int idx = tid; idx < 4 * 10 * 130; idx += 256) {
            int c = idx % 130; int r = (idx / 130) % 10; int icc = idx / 1300;
            int gy = y0 - 1 + r, gx = xbase - 1 + c;
            float v = 0.f;
            if (gy >= 0 && gy < 256 && gx >= 0 && gx < 256)
                v = g_u2[(((size_t)b * 64 + ic0 + icc) * 256 + gy) * 256 + gx];
            sin_[icc][r][c] = v;
        }
        __syncthreads();
        for (int icc = 0; icc < 4; icc++) {
#pragma unroll
            for (int ky = 0; ky < 3; ky++) {
                float in6[6];
#pragma unroll
                for (int t = 0; t < 6; t++) in6[t] = sin_[icc][yr + ky][x0 + t];
#pragma unroll
                for (int kx = 0; kx < 3; kx++) {
#pragma unroll
                    for (int oc = 0; oc < 3; oc++) {
                        float wv = sw[(oc * 64 + ic0 + icc) * 9 + ky * 3 + kx];
#pragma unroll
                        for (int xi = 0; xi < 4; xi++)
                            acc[oc][xi] += wv * in6[kx + xi];
                    }
                }
            }
        }
    }
    int gy = y0 + yr, gx0 = xbase + x0;
#pragma unroll
    for (int oc = 0; oc < 3; oc++) {
        float4 v = make_float4(acc[oc][0], acc[oc][1], acc[oc][2], acc[oc][3]);
        *(float4*)&out[(((size_t)b * 3 + oc) * 256 + gy) * 256 + gx0] = v;
    }
}

// ---------------- launcher ----------------
extern "C" void kernel_launch(void* const* d_in, const int* in_sizes, int n_in,
                              void* d_out, int out_size) {
    const float* x      = (const float*)d_in[0];
    const float* th     = (const float*)d_in[1];
    const float* proj_w = (const float*)d_in[2];
    const float* proj_b = (const float*)d_in[3];
    const float* cf_w   = (const float*)d_in[4];
    const float* cf_b   = (const float*)d_in[5];
    const float* qw     = (const float*)d_in[6];
    const float* qb     = (const float*)d_in[7];
    const float* kw     = (const float*)d_in[8];
    const float* kb     = (const float*)d_in[9];
    const float* vw     = (const float*)d_in[10];
    const float* vb     = (const float*)d_in[11];
    const float* ow     = (const float*)d_in[12];
    const float* ob     = (const float*)d_in[13];
    const float* l1w    = (const float*)d_in[14];
    const float* l1b    = (const float*)d_in[15];
    const float* l2w    = (const float*)d_in[16];
    const float* l2b    = (const float*)d_in[17];
    const float* up_w   = (const float*)d_in[18];
    const float* up_b   = (const float*)d_in[19];
    const float* cl_w   = (const float*)d_in[20];
    const float* cl_b   = (const float*)d_in[21];
    float* out = (float*)d_out;

    k_textproj<<<BATCH * LSEQ, 64>>>(th, proj_w, proj_b, up_w);
    k_convin<<<BATCH * HH, 64>>>(x, cf_w, cf_b);
    k_kvall<<<dim3(NBLK, BATCH, 2), 256>>>(kw, kb, vw, vb, l2w, l2b);
    k_attn_stack<<<BATCH * HH, 256>>>(qw, qb, ow, ob, l1w, l1b);
    k_upconv_tc<<<dim3(4, 8, BATCH * 4), 256>>>(0, 64, 64, up_b);
    k_upconv_tc<<<dim3(8, 16, BATCH * 4), 256>>>(1, 128, 128, up_b);
    k_cl<<<dim3(2, 32, BATCH), 256>>>(cl_w, cl_b, out);

    (void)in_sizes; (void)n_in; (void)out_size;
}

// round 7
// speedup vs baseline: 1.1723x; 1.1723x over previous
#include <cuda_runtime.h>
#include <cuda_bf16.h>
#include <cstdint>

// ---------------- problem constants ----------------
#define BATCH 8
#define CCH   64
#define HH    64
#define WW    64
#define NPOS  4096
#define LSEQ  77
#define DTXT  512
#define NBLK  16
#define NHEAD 8
#define HDIM  8

// ---------------- device scratch ----------------
__device__ float g_tf  [BATCH*LSEQ*CCH];
__device__ float g_kn  [NBLK*BATCH*LSEQ*CCH];
__device__ float g_v   [NBLK*BATCH*LSEQ*CCH];
__device__ float g_feat[BATCH*CCH*HH*WW];
__device__ float g_u1  [BATCH*CCH*128*128];
__device__ float g_u2  [(size_t)BATCH*CCH*256*256];
__device__ float g_wupT[2*9*4*64*64];   // [lvl][tap][ocg][oc(64)][ic(64)], tf32

__device__ __forceinline__ float to_tf32(float x) {
    float r; asm("cvt.rna.tf32.f32 %0, %1;" : "=f"(r) : "f"(x)); return r;
}
__device__ __forceinline__ void mma_tf32(float* d, const uint32_t* a, const uint32_t* b) {
    asm volatile(
        "mma.sync.aligned.m16n8k8.row.col.f32.tf32.tf32.f32 "
        "{%0,%1,%2,%3}, {%4,%5,%6,%7}, {%8,%9}, {%0,%1,%2,%3};"
        : "+f"(d[0]), "+f"(d[1]), "+f"(d[2]), "+f"(d[3])
        : "r"(a[0]), "r"(a[1]), "r"(a[2]), "r"(a[3]), "r"(b[0]), "r"(b[1]));
}
// permuted channel index: ic = ks*8 + tig + 4h  ->  pic = ks*8 + tig*2 + h
__device__ __forceinline__ int picf(int ic) {
    int r = ic & 7;
    return (ic & ~7) + ((r & 3) * 2) + (r >> 2);
}

// ---------------- text projection (+ fused tf32 up-weight transpose) ----------------
__global__ void k_textproj(const float* __restrict__ th,
                           const float* __restrict__ pw,
                           const float* __restrict__ pb,
                           const float* __restrict__ upw) {
    __shared__ float s[DTXT];
    int bl = blockIdx.x;
    const float* row = th + (size_t)bl * DTXT;
    for (int i = threadIdx.x; i < DTXT; i += 64) s[i] = row[i];
    __syncthreads();
    int c = threadIdx.x;
    const float* w = pw + (size_t)c * DTXT;
    float acc = pb[c];
#pragma unroll 8
    for (int d = 0; d < DTXT; ++d) acc += s[d] * w[d];
    g_tf[bl * CCH + c] = acc;
    // transpose up weights [lvl,oc4,ic,k] -> [lvl,k,ocg,oc,ic], tf32-rounded
    for (int idx = blockIdx.x * 64 + threadIdx.x; idx < 2 * 256 * 64 * 9;
         idx += gridDim.x * 64) {
        int k = idx % 9;
        int t = idx / 9;
        int ic = t % 64; t /= 64;
        int oc4 = t % 256;
        int lvl = t / 256;
        g_wupT[((((lvl * 9 + k) * 4 + (oc4 >> 6)) * 64 + (oc4 & 63)) * 64) + ic]
            = to_tf32(upw[idx]);
    }
}

// ---------------- input conv 3->64, 3x3 ----------------
__global__ void k_convin(const float* __restrict__ x,
                         const float* __restrict__ w,
                         const float* __restrict__ bias) {
    __shared__ float sw[64 * 27];
    __shared__ float sb[64];
    __shared__ float sin_[3][3][66];
    int bid = blockIdx.x; int b = bid >> 6; int y = bid & 63;
    int tid = threadIdx.x;
    for (int i = tid; i < 64 * 27; i += 64) sw[i] = w[i];
    sb[tid] = bias[tid];
    for (int ic = 0; ic < 3; ic++)
        for (int r = 0; r < 3; r++) {
            int yy = y + r - 1;
            float v = 0.f;
            if (yy >= 0 && yy < HH) v = x[(((size_t)b * 3 + ic) * HH + yy) * WW + tid];
            sin_[ic][r][tid + 1] = v;
            if (tid == 0) { sin_[ic][r][0] = 0.f; sin_[ic][r][65] = 0.f; }
        }
    __syncthreads();
    int xx = tid;
    for (int oc = 0; oc < 64; oc++) {
        float acc = sb[oc];
#pragma unroll
        for (int ic = 0; ic < 3; ic++)
#pragma unroll
            for (int r = 0; r < 3; r++)
#pragma unroll
                for (int kx = 0; kx < 3; kx++)
                    acc += sin_[ic][r][xx + kx] * sw[(oc * 3 + ic) * 9 + r * 3 + kx];
        g_feat[(((size_t)b * CCH + oc) * HH + y) * WW + xx] = acc;
    }
}

// ---------------- K/V projection + LN(K), all blocks, L-split ----------------
__global__ void __launch_bounds__(256) k_kvall(
        const float* __restrict__ kw, const float* __restrict__ kb,
        const float* __restrict__ vw, const float* __restrict__ vb,
        const float* __restrict__ l2w, const float* __restrict__ l2b) {
    __shared__ float tfs[LSEQ * 64];
    __shared__ float kws[64 * 68];
    __shared__ float vws[64 * 68];
    __shared__ float ksm[4 * 64];
    int blk = blockIdx.x, b = blockIdx.y, z = blockIdx.z;
    int tid = threadIdx.x;
    for (int i = tid; i < LSEQ * 64; i += 256) tfs[i] = g_tf[b * LSEQ * 64 + i];
    for (int idx = tid; idx < 4096; idx += 256) {
        int o = idx >> 6, c = idx & 63;
        kws[c * 68 + o] = kw[blk * 4096 + idx];
        vws[c * 68 + o] = vw[blk * 4096 + idx];
    }
    __syncthreads();
    int o = tid & 63, rr = tid >> 6;
    float kbv = kb[blk * 64 + o], vbv = vb[blk * 64 + o];
    float lwv = l2w[blk * 64 + o], lbv = l2b[blk * 64 + o];
    size_t base = ((size_t)(blk * BATCH + b)) * LSEQ * 64;
    int rbeg = z * 40, rend = rbeg + 40;
    for (int r0 = rbeg; r0 < rend; r0 += 4) {
        int r = r0 + rr;
        bool act = r < LSEQ;
        float ka = kbv, va = vbv;
        if (act) {
#pragma unroll 8
            for (int c = 0; c < 64; c++) {
                float t = tfs[r * 64 + c];
                ka += t * kws[c * 68 + o];
                va += t * vws[c * 68 + o];
            }
            ksm[rr * 64 + o] = ka;
        }
        __syncthreads();
        if (act) {
            float m = 0.f;
#pragma unroll 8
            for (int i = 0; i < 64; i++) m += ksm[rr * 64 + i];
            m *= (1.f / 64.f);
            float vv = 0.f;
#pragma unroll 8
            for (int i = 0; i < 64; i++) { float d = ksm[rr * 64 + i] - m; vv += d * d; }
            vv *= (1.f / 64.f);
            float rs = rsqrtf(vv + 1e-5f);
            g_kn[base + r * 64 + o] = (ka - m) * rs * lwv + lbv;
            g_v [base + r * 64 + o] = va;
        }
        __syncthreads();
    }
}

// ---------------- FUSED attention stack (16 blocks, one launch) ----------------
__global__ void __launch_bounds__(256, 3) k_attn_stack(
        const float* __restrict__ qw, const float* __restrict__ qb,
        const float* __restrict__ ow, const float* __restrict__ ob,
        const float* __restrict__ l1w, const float* __restrict__ l1b) {
    __shared__ __align__(16) float rA[LSEQ * 64];   // Wq | K
    __shared__ __align__(16) float rB[LSEQ * 64];   // V | Wo
    __shared__ __align__(16) float sF[64 * 64];
    __shared__ __align__(16) float sQ[64 * 68];

    int b = blockIdx.x >> 6, y = blockIdx.x & 63;
    int tid = threadIdx.x;

    for (int idx = tid; idx < 4096; idx += 256)
        sF[idx] = g_feat[(((size_t)b * 64 + (idx >> 6)) * 64 + y) * 64 + (idx & 63)];

    float pey = (float)y * (0.05f / 63.f);
    const float scale = 0.35355339059327373f;

#pragma unroll 1
    for (int blk = 0; blk < NBLK; blk++) {
        size_t kvbase = ((size_t)(blk * BATCH + b)) * LSEQ * 64;
        __syncthreads();
        for (int idx = tid; idx < 4096; idx += 256) {
            int o = idx >> 6, i = idx & 63;
            rA[i * 68 + o] = qw[blk * 4096 + idx];
        }
        for (int i = tid; i < LSEQ * 64; i += 256) rB[i] = g_v[kvbase + i];
        __syncthreads();

        // ---- phase B: q-proj + pe + LN ----
        {
            int og = tid & 15, xg = tid >> 4;
            int o0 = og * 4, x0 = xg * 4;
            float4 bq = *(const float4*)&qb[blk * 64 + o0];
            float acc[4][4];
#pragma unroll
            for (int xi = 0; xi < 4; xi++) {
                acc[xi][0] = bq.x; acc[xi][1] = bq.y; acc[xi][2] = bq.z; acc[xi][3] = bq.w;
            }
#pragma unroll 8
            for (int i = 0; i < 64; i++) {
                float4 fx = *(const float4*)&sF[i * 64 + x0];
                float4 wv = *(const float4*)&rA[i * 68 + o0];
                acc[0][0] += fx.x * wv.x; acc[0][1] += fx.x * wv.y; acc[0][2] += fx.x * wv.z; acc[0][3] += fx.x * wv.w;
                acc[1][0] += fx.y * wv.x; acc[1][1] += fx.y * wv.y; acc[1][2] += fx.y * wv.z; acc[1][3] += fx.y * wv.w;
                acc[2][0] += fx.z * wv.x; acc[2][1] += fx.z * wv.y; acc[2][2] += fx.z * wv.z; acc[2][3] += fx.z * wv.w;
                acc[3][0] += fx.w * wv.x; acc[3][1] += fx.w * wv.y; acc[3][2] += fx.w * wv.z; acc[3][3] += fx.w * wv.w;
            }
            float4 lw = *(const float4*)&l1w[blk * 64 + o0];
            float4 lb = *(const float4*)&l1b[blk * 64 + o0];
#pragma unroll
            for (int xi = 0; xi < 4; xi++) {
                float pex = (float)(x0 + xi) * (0.05f / 63.f);
#pragma unroll
                for (int oj = 0; oj < 4; oj++)
                    acc[xi][oj] += ((o0 + oj) < 32) ? pex : pey;
                float s = acc[xi][0] + acc[xi][1] + acc[xi][2] + acc[xi][3];
#pragma unroll
                for (int off = 1; off < 16; off <<= 1) s += __shfl_xor_sync(0xffffffffu, s, off);
                float mean = s * (1.f / 64.f);
                float d0 = acc[xi][0] - mean, d1 = acc[xi][1] - mean,
                      d2 = acc[xi][2] - mean, d3 = acc[xi][3] - mean;
                float sq = d0 * d0 + d1 * d1 + d2 * d2 + d3 * d3;
#pragma unroll
                for (int off = 1; off < 16; off <<= 1) sq += __shfl_xor_sync(0xffffffffu, sq, off);
                float rs = rsqrtf(sq * (1.f / 64.f) + 1e-5f);
                float4 outv;
                outv.x = d0 * rs * lw.x + lb.x;
                outv.y = d1 * rs * lw.y + lb.y;
                outv.z = d2 * rs * lw.z + lb.z;
                outv.w = d3 * rs * lw.w + lb.w;
                *(float4*)&sQ[(x0 + xi) * 68 + o0] = outv;
            }
        }
        __syncthreads();
        for (int i = tid; i < LSEQ * 64; i += 256) rA[i] = g_kn[kvbase + i];
        __syncthreads();

        // ---- phase C: attention (tree-reduced logits) ----
        {
            int hp = tid & 3, pl = tid >> 2;
            int co = hp * 16;
            const float4* qp = (const float4*)&sQ[pl * 68 + co];
            float4 qa0 = qp[0], qa1 = qp[1], qb0 = qp[2], qb1 = qp[3];
            __syncthreads();
            float denA = 0.f, denB = 0.f;
            float4 a0 = make_float4(0, 0, 0, 0), a1 = a0, b0 = a0, b1 = a0;
#pragma unroll 2
            for (int l = 0; l < LSEQ; l++) {
                const float4* kp = (const float4*)&rA[l * 64 + co];
                float4 k0 = kp[0], k1 = kp[1], k2 = kp[2], k3 = kp[3];
                float tA0 = qa0.x * k0.x + qa0.y * k0.y;
                float tA1 = qa0.z * k0.z + qa0.w * k0.w;
                float tA2 = qa1.x * k1.x + qa1.y * k1.y;
                float tA3 = qa1.z * k1.z + qa1.w * k1.w;
                float tB0 = qb0.x * k2.x + qb0.y * k2.y;
                float tB1 = qb0.z * k2.z + qb0.w * k2.w;
                float tB2 = qb1.x * k3.x + qb1.y * k3.y;
                float tB3 = qb1.z * k3.z + qb1.w * k3.w;
                float lgA = (tA0 + tA1) + (tA2 + tA3);
                float lgB = (tB0 + tB1) + (tB2 + tB3);
                float eA = __expf(lgA * scale);
                float eB = __expf(lgB * scale);
                denA += eA; denB += eB;
                const float4* vp = (const float4*)&rB[l * 64 + co];
                float4 v0 = vp[0], v1 = vp[1], v2 = vp[2], v3 = vp[3];
                a0.x += eA * v0.x; a0.y += eA * v0.y; a0.z += eA * v0.z; a0.w += eA * v0.w;
                a1.x += eA * v1.x; a1.y += eA * v1.y; a1.z += eA * v1.z; a1.w += eA * v1.w;
                b0.x += eB * v2.x; b0.y += eB * v2.y; b0.z += eB * v2.z; b0.w += eB * v2.w;
                b1.x += eB * v3.x; b1.y += eB * v3.y; b1.z += eB * v3.z; b1.w += eB * v3.w;
            }
            float iA = 1.f / denA, iB = 1.f / denB;
            sQ[(co + 0) * 68 + pl] = a0.x * iA;  sQ[(co + 1) * 68 + pl] = a0.y * iA;
            sQ[(co + 2) * 68 + pl] = a0.z * iA;  sQ[(co + 3) * 68 + pl] = a0.w * iA;
            sQ[(co + 4) * 68 + pl] = a1.x * iA;  sQ[(co + 5) * 68 + pl] = a1.y * iA;
            sQ[(co + 6) * 68 + pl] = a1.z * iA;  sQ[(co + 7) * 68 + pl] = a1.w * iA;
            sQ[(co + 8) * 68 + pl] = b0.x * iB;  sQ[(co + 9) * 68 + pl] = b0.y * iB;
            sQ[(co + 10) * 68 + pl] = b0.z * iB; sQ[(co + 11) * 68 + pl] = b0.w * iB;
            sQ[(co + 12) * 68 + pl] = b1.x * iB; sQ[(co + 13) * 68 + pl] = b1.y * iB;
            sQ[(co + 14) * 68 + pl] = b1.z * iB; sQ[(co + 15) * 68 + pl] = b1.w * iB;
        }
        __syncthreads();
        for (int idx = tid; idx < 4096; idx += 256) {
            int o = idx >> 6, i = idx & 63;
            rB[i * 68 + o] = ow[blk * 4096 + idx];
        }
        __syncthreads();

        // ---- phase E: out-proj + residual ----
        {
            int xg = tid & 15, og = tid >> 4;
            int x0 = xg * 4, o0 = og * 4;
            float acc[4][4];
#pragma unroll
            for (int oj = 0; oj < 4; oj++)
#pragma unroll
                for (int xi = 0; xi < 4; xi++) acc[oj][xi] = 0.f;
#pragma unroll 8
            for (int i = 0; i < 64; i++) {
                float4 fx = *(const float4*)&sQ[i * 68 + x0];
                float4 wv = *(const float4*)&rB[i * 68 + o0];
                acc[0][0] += wv.x * fx.x; acc[0][1] += wv.x * fx.y; acc[0][2] += wv.x * fx.z; acc[0][3] += wv.x * fx.w;
                acc[1][0] += wv.y * fx.x; acc[1][1] += wv.y * fx.y; acc[1][2] += wv.y * fx.z; acc[1][3] += wv.y * fx.w;
                acc[2][0] += wv.z * fx.x; acc[2][1] += wv.z * fx.y; acc[2][2] += wv.z * fx.z; acc[2][3] += wv.z * fx.w;
                acc[3][0] += wv.w * fx.x; acc[3][1] += wv.w * fx.y; acc[3][2] += wv.w * fx.z; acc[3][3] += wv.w * fx.w;
            }
            float4 bo = *(const float4*)&ob[blk * 64 + o0];
            float bov[4] = { bo.x, bo.y, bo.z, bo.w };
            __syncthreads();
#pragma unroll
            for (int oj = 0; oj < 4; oj++) {
                float* fp = &sF[(o0 + oj) * 64 + x0];
                float4 f = *(float4*)fp;
                f.x += acc[oj][0] + bov[oj];
                f.y += acc[oj][1] + bov[oj];
                f.z += acc[oj][2] + bov[oj];
                f.w += acc[oj][3] + bov[oj];
                *(float4*)fp = f;
            }
        }
    }
    __syncthreads();
    for (int idx = tid; idx < 4096; idx += 256)
        g_feat[(((size_t)b * 64 + (idx >> 6)) * 64 + y) * 64 + (idx & 63)] = sF[idx];
}

// ---------------- TF32 tensor-core up-conv + pixel-shuffle + relu ----------------
// Conflict-free float2 fragment loads: smem stride 72 (== 8 mod 32).
__global__ void __launch_bounds__(256, 3) k_upconv_tc(int lvl, int IH, int IW,
                                                      const float* __restrict__ up_b) {
    const float* in   = lvl ? g_u1 : g_feat;
    float*       outp = lvl ? g_u2 : g_u1;
    __shared__ float sA[180 * 72];   // [spatial r*18+c][pic(ic)], stride 72
    __shared__ float sBT[64 * 72];   // [oc][pic(ic)], stride 72
    int x0 = blockIdx.x * 16, y0 = blockIdx.y * 8;
    int bz = blockIdx.z; int b = bz >> 2, ocg = bz & 3;
    int tid = threadIdx.x;
    int w = tid >> 5, lane = tid & 31;
    int g = lane >> 2, tig = lane & 3;
    int wm = w & 3, wn = w >> 2;

    // stage input tile with halo (tf32-rounded, permuted channels)
    for (int idx = tid; idx < 180 * 64; idx += 256) {
        int ic = idx / 180; int sp = idx % 180;
        int r = sp / 18, c = sp % 18;
        int gy = y0 - 1 + r, gx = x0 - 1 + c;
        float v = 0.f;
        if (gy >= 0 && gy < IH && gx >= 0 && gx < IW)
            v = in[(((size_t)b * 64 + ic) * IH + gy) * IW + gx];
        sA[sp * 72 + picf(ic)] = to_tf32(v);
    }

    float d[2][4][4];
#pragma unroll
    for (int nt = 0; nt < 4; nt++) {
        int oc = ocg * 64 + wn * 32 + nt * 8 + tig * 2;
        float b0v = up_b[lvl * 256 + oc];
        float b1v = up_b[lvl * 256 + oc + 1];
#pragma unroll
        for (int mt = 0; mt < 2; mt++) {
            d[mt][nt][0] = b0v; d[mt][nt][1] = b1v;
            d[mt][nt][2] = b0v; d[mt][nt][3] = b1v;
        }
    }

#pragma unroll 1
    for (int t = 0; t < 9; t++) {
        int ky = t / 3, kx = t % 3;
        __syncthreads();
        // stage weights: consecutive ic (coalesced gmem), conflict-free smem stores
        for (int idx = tid; idx < 4096; idx += 256) {
            int ic = idx & 63, oc = idx >> 6;
            sBT[oc * 72 + picf(ic)] =
                g_wupT[((((lvl * 9 + t) * 4 + ocg) * 64 + oc) * 64) + ic];
        }
        __syncthreads();
        int sp_base[2][2];
#pragma unroll
        for (int mt = 0; mt < 2; mt++) {
            int m_lo = wm * 32 + mt * 16 + g;
            int m_hi = m_lo + 8;
            sp_base[mt][0] = ((m_lo >> 4) + ky) * 18 + (m_lo & 15) + kx;
            sp_base[mt][1] = ((m_hi >> 4) + ky) * 18 + (m_hi & 15) + kx;
        }
#pragma unroll
        for (int ks = 0; ks < 8; ks++) {
            int po = ks * 8 + tig * 2;
            uint32_t A[2][4];
#pragma unroll
            for (int mt = 0; mt < 2; mt++) {
                float2 lo = *(const float2*)&sA[sp_base[mt][0] * 72 + po];
                float2 hi = *(const float2*)&sA[sp_base[mt][1] * 72 + po];
                A[mt][0] = __float_as_uint(lo.x);
                A[mt][1] = __float_as_uint(hi.x);
                A[mt][2] = __float_as_uint(lo.y);
                A[mt][3] = __float_as_uint(hi.y);
            }
            uint32_t Bf[4][2];
#pragma unroll
            for (int nt = 0; nt < 4; nt++) {
                int nc = wn * 32 + nt * 8 + g;
                float2 bv = *(const float2*)&sBT[nc * 72 + po];
                Bf[nt][0] = __float_as_uint(bv.x);
                Bf[nt][1] = __float_as_uint(bv.y);
            }
#pragma unroll
            for (int mt = 0; mt < 2; mt++)
#pragma unroll
                for (int nt = 0; nt < 4; nt++)
                    mma_tf32(d[mt][nt], A[mt], Bf[nt]);
        }
    }

    int OW = IW * 2;
#pragma unroll
    for (int mt = 0; mt < 2; mt++) {
#pragma unroll
        for (int half = 0; half < 2; half++) {
            int m = wm * 32 + mt * 16 + g + half * 8;
            int gy = y0 + (m >> 4), gx = x0 + (m & 15);
#pragma unroll
            for (int nt = 0; nt < 4; nt++) {
                int oc4a = ocg * 64 + wn * 32 + nt * 8 + tig * 2;
                float v0 = d[mt][nt][half * 2 + 0];
                float v1 = d[mt][nt][half * 2 + 1];
                int ca = oc4a >> 2, r1a = (oc4a >> 1) & 1, r2a = oc4a & 1;
                int oc4b = oc4a + 1;
                int cb = oc4b >> 2, r1b = (oc4b >> 1) & 1, r2b = oc4b & 1;
                outp[(((size_t)b * 64 + ca) * (size_t)(IH * 2) + (size_t)(2 * gy + r1a)) * (size_t)OW
                     + 2 * gx + r2a] = fmaxf(v0, 0.f);
                outp[(((size_t)b * 64 + cb) * (size_t)(IH * 2) + (size_t)(2 * gy + r1b)) * (size_t)OW
                     + 2 * gx + r2b] = fmaxf(v1, 0.f);
            }
        }
    }
}

// ---------------- final conv 64->3 at 256x256 ----------------
__global__ void __launch_bounds__(256) k_cl(const float* __restrict__ w,
                                            const float* __restrict__ bias,
                                            float* __restrict__ out) {
    __shared__ float sw[3 * 64 * 9];
    __shared__ float sin_[4][10][132];
    int xbase = blockIdx.x * 128;
    int y0 = blockIdx.y * 8;
    int b = blockIdx.z;
    int tid = threadIdx.x;
    int xg = tid & 31; int yr = tid >> 5;
    int x0 = xg * 4;
    for (int i = tid; i < 1728; i += 256) sw[i] = w[i];
    float acc[3][4];
#pragma unroll
    for (int oc = 0; oc < 3; oc++) {
        float bb = bias[oc];
#pragma unroll
        for (int xi = 0; xi < 4; xi++) acc[oc][xi] = bb;
    }
    for (int ic0 = 0; ic0 < 64; ic0 += 4) {
        __syncthreads();
        for (int idx = tid; idx < 4 * 10 * 130; idx += 256) {
            int c = idx % 130; int r = (idx / 130) % 10; int icc = idx / 1300;
            int gy = y0 - 1 + r, gx = xbase - 1 + c;
            float v = 0.f;
            if (gy >= 0 && gy < 256 && gx >= 0 && gx < 256)
                v = g_u2[(((size_t)b * 64 + ic0 + icc) * 256 + gy) * 256 + gx];
            sin_[icc][r][c] = v;
        }
        __syncthreads();
        for (int icc = 0; icc < 4; icc++) {
#pragma unroll
            for (int ky = 0; ky < 3; ky++) {
                float in6[6];
#pragma unroll
                for (int t = 0; t < 6; t++) in6[t] = sin_[icc][yr + ky][x0 + t];
#pragma unroll
                for (int kx = 0; kx < 3; kx++) {
#pragma unroll
                    for (int oc = 0; oc < 3; oc++) {
                        float wv = sw[(oc * 64 + ic0 + icc) * 9 + ky * 3 + kx];
#pragma unroll
                        for (int xi = 0; xi < 4; xi++)
                            acc[oc][xi] += wv * in6[kx + xi];
                    }
                }
            }
        }
    }
    int gy = y0 + yr, gx0 = xbase + x0;
#pragma unroll
    for (int oc = 0; oc < 3; oc++) {
        float4 v = make_float4(acc[oc][0], acc[oc][1], acc[oc][2], acc[oc][3]);
        *(float4*)&out[(((size_t)b * 3 + oc) * 256 + gy) * 256 + gx0] = v;
    }
}

// ---------------- launcher ----------------
extern "C" void kernel_launch(void* const* d_in, const int* in_sizes, int n_in,
                              void* d_out, int out_size) {
    const float* x      = (const float*)d_in[0];
    const float* th     = (const float*)d_in[1];
    const float* proj_w = (const float*)d_in[2];
    const float* proj_b = (const float*)d_in[3];
    const float* cf_w   = (const float*)d_in[4];
    const float* cf_b   = (const float*)d_in[5];
    const float* qw     = (const float*)d_in[6];
    const float* qb     = (const float*)d_in[7];
    const float* kw     = (const float*)d_in[8];
    const float* kb     = (const float*)d_in[9];
    const float* vw     = (const float*)d_in[10];
    const float* vb     = (const float*)d_in[11];
    const float* ow     = (const float*)d_in[12];
    const float* ob     = (const float*)d_in[13];
    const float* l1w    = (const float*)d_in[14];
    const float* l1b    = (const float*)d_in[15];
    const float* l2w    = (const float*)d_in[16];
    const float* l2b    = (const float*)d_in[17];
    const float* up_w   = (const float*)d_in[18];
    const float* up_b   = (const float*)d_in[19];
    const float* cl_w   = (const float*)d_in[20];
    const float* cl_b   = (const float*)d_in[21];
    float* out = (float*)d_out;

    k_textproj<<<BATCH * LSEQ, 64>>>(th, proj_w, proj_b, up_w);
    k_convin<<<BATCH * HH, 64>>>(x, cf_w, cf_b);
    k_kvall<<<dim3(NBLK, BATCH, 2), 256>>>(kw, kb, vw, vb, l2w, l2b);
    k_attn_stack<<<BATCH * HH, 256>>>(qw, qb, ow, ob, l1w, l1b);
    k_upconv_tc<<<dim3(4, 8, BATCH * 4), 256>>>(0, 64, 64, up_b);
    k_upconv_tc<<<dim3(8, 16, BATCH * 4), 256>>>(1, 128, 128, up_b);
    k_cl<<<dim3(2, 32, BATCH), 256>>>(cl_w, cl_b, out);

    (void)in_sizes; (void)n_in; (void)out_size;
}